// round 16
// baseline (speedup 1.0000x reference)
#include <cuda_runtime.h>
#include <math.h>

#define NB    300
#define BATCH 8
#define RSEL  36
#define NW    10
#define CCH   256
#define GRID  14
#define SPAN  64
#define NSEL  (BATCH * RSEL)
#define NCGB  32             // channel-group blocks (8 channels each)
#define CONF_THR 0.3f
#define IOU_THR  0.7f

// Inter-kernel scratch (device globals; no allocations allowed)
__device__ float4   g_sbox[BATCH * NB];       // sorted boxes
__device__ unsigned g_vinit[BATCH * NW];      // initial keep words (validity)
__device__ unsigned g_sup[BATCH * NB * NW];   // suppression masks
__device__ float    g_cx[NSEL * SPAN];        // x coefficients (range form)
__device__ float    g_cy[NSEL * SPAN];        // y coefficients (COMPACTED values)
__device__ int      g_cyi[NSEL * SPAN];       // y row indices (COMPACTED, rel ylo)
__device__ int      g_meta[NSEL * 8];         // xlo,Lx,ylo,Ly,valid,lv,Lc,0

// ---------------------------------------------------------------------------
// K12: threshold + stable sort + suppression-mask word. Grid (NW, BATCH) x 320.
// (R9/R14 proven configuration, unchanged.)
// ---------------------------------------------------------------------------
__global__ void k12_mask(const float* __restrict__ boxes,
                         const float* __restrict__ scores)
{
    const int w = blockIdx.x;
    const int b = blockIdx.y;
    const int t = threadIdx.x;

    __shared__ float  s_raw[NB];
    __shared__ int    s_order[NB];
    __shared__ float4 s_box[NB];
    __shared__ float  s_area[NB];
    __shared__ float  s_ss[NB];

    for (int i = t; i < NB; i += blockDim.x) {
        float sc = scores[b * NB + i];
        s_raw[i] = (sc > CONF_THR) ? sc : -INFINITY;
    }
    __syncthreads();

    for (int i = t; i < NB; i += blockDim.x) {
        float si = s_raw[i];
        int rank = 0;
        for (int j = 0; j < NB; j++) {
            float sj = s_raw[j];
            if (sj > si || (sj == si && j < i)) rank++;
        }
        s_order[rank] = i;
    }
    __syncthreads();

    for (int r = t; r < NB; r += blockDim.x) {
        int i = s_order[r];
        float4 bb = ((const float4*)boxes)[(size_t)b * NB + i];
        s_box[r]  = bb;
        s_area[r] = (bb.z - bb.x) * (bb.w - bb.y);
        s_ss[r]   = s_raw[i];
    }
    __syncthreads();

    if (w == 0) {
        for (int r = t; r < NB; r += blockDim.x)
            g_sbox[b * NB + r] = s_box[r];
        int pred = (t < NB) && (s_ss[t] > -INFINITY);
        unsigned word = __ballot_sync(0xffffffffu, pred);
        if ((t & 31) == 0) g_vinit[b * NW + (t >> 5)] = word;
    }

    const int i = t;
    if (i >= NB) return;

    unsigned bits = 0;
    if (w * 32 + 31 > i) {
        float4 a = s_box[i];
        float area_a = s_area[i];
        #pragma unroll 4
        for (int k = 0; k < 32; k++) {
            int j = w * 32 + k;
            if (j < NB && j > i) {
                float4 bb = s_box[j];
                float ltx = fmaxf(a.x, bb.x);
                float lty = fmaxf(a.y, bb.y);
                float rbx = fminf(a.z, bb.z);
                float rby = fminf(a.w, bb.w);
                float iw = fmaxf(rbx - ltx, 0.0f);
                float ih = fmaxf(rby - lty, 0.0f);
                float inter = iw * ih;
                float iou = inter / (area_a + s_area[j] - inter + 1e-9f);
                if (iou > IOU_THR) bits |= (1u << k);
            }
        }
    }
    g_sup[(b * NB + i) * NW + w] = bits;
}

// ---------------------------------------------------------------------------
// K3: suppression + selection + level + coefficients (+ cy compaction).
// 8 blocks x 320.
// ---------------------------------------------------------------------------
__global__ void k3_final()
{
    const int b = blockIdx.x;
    const int t = threadIdx.x;

    __shared__ unsigned s_sup[NB][NW];
    __shared__ unsigned s_keepw[NW];
    __shared__ int      s_sel[RSEL];
    __shared__ float4   s_selbox[RSEL];
    __shared__ float    s_coef[RSEL][2][SPAN];
    __shared__ int      s_cyi[RSEL][SPAN];

    for (int e = t; e < NB * NW; e += blockDim.x)
        ((unsigned*)s_sup)[e] = g_sup[b * NB * NW + e];
    if (t < NW) s_keepw[t] = g_vinit[b * NW + t];
    for (int e = t; e < RSEL * 2 * SPAN; e += blockDim.x)
        ((float*)s_coef)[e] = 0.0f;
    __syncthreads();

    if (t < 32) {
        unsigned keepw = (t < NW) ? s_keepw[t] : 0u;
        for (int i = 0; i < NB; i++) {
            unsigned wv = __shfl_sync(0xffffffffu, keepw, i >> 5);
            if ((wv >> (i & 31)) & 1u) {
                if (t < NW) keepw &= ~s_sup[i][t];
            }
        }
        if (t < NW) s_keepw[t] = keepw;
    }
    __syncthreads();

    if (t == 0) {
        int cnt = 0;
        for (int w = 0; w < NW && cnt < RSEL; w++) {
            unsigned bits = s_keepw[w];
            while (bits && cnt < RSEL) {
                int k = __ffs(bits) - 1; bits &= bits - 1;
                s_sel[cnt++] = w * 32 + k;
            }
        }
        for (int w = 0; w < NW && cnt < RSEL; w++) {
            unsigned bits = ~s_keepw[w];
            if (w == NW - 1) bits &= (1u << (NB - (NW - 1) * 32)) - 1;
            while (bits && cnt < RSEL) {
                int k = __ffs(bits) - 1; bits &= bits - 1;
                s_sel[cnt++] = w * 32 + k;
            }
        }
    }
    __syncthreads();

    if (t < RSEL) {
        int j = s_sel[t];
        float4 bb = g_sbox[b * NB + j];
        s_selbox[t] = bb;
        int valid = (s_keepw[j >> 5] >> (j & 31)) & 1u;
        float dx = bb.z - bb.x, dy = bb.w - bb.y;
        float sz = sqrtf(fmaxf(dx * dx + dy * dy, 1e-12f));
        float lvf = fminf(fmaxf(floorf(4.0f + log2f(sz / 224.0f * 4.0f)), 2.0f), 5.0f);
        int base = (b * RSEL + t) * 8;
        g_meta[base + 4] = valid;
        g_meta[base + 5] = (int)lvf - 2;
        g_meta[base + 6] = 0;
        g_meta[base + 7] = 0;
    }
    __syncthreads();

    // coefficient build: task t -> (box r = t>>1, axis = t&1); cy compacted
    if (t < 2 * RSEL) {
        const int r = t >> 1, axis = t & 1;
        float4 bb = s_selbox[r];
        float dx = bb.z - bb.x, dy = bb.w - bb.y;
        float sz = sqrtf(fmaxf(dx * dx + dy * dy, 1e-12f));
        float lvf = fminf(fmaxf(floorf(4.0f + log2f(sz / 224.0f * 4.0f)), 2.0f), 5.0f);
        int lv = (int)lvf - 2;
        int H = 200 >> lv;
        float c1 = axis ? bb.y : bb.x;
        float c2 = axis ? bb.w : bb.z;
        float rs = fmaxf(c2 - c1, 1.0f);

        int lo = 1 << 30, hi = -(1 << 30);
        #pragma unroll
        for (int s = 0; s < GRID; s++) {
            float g = ((float)s + 0.5f) / (float)GRID;
            float P = c1 + rs * g;
            if (P < -1.0f || P > (float)H) continue;
            float p = fminf(fmaxf(P, 0.0f), (float)(H - 1));
            int p0 = (int)floorf(p);
            int p1 = min(p0 + 1, H - 1);
            lo = min(lo, p0); hi = max(hi, p1);
        }
        int L;
        if (lo > hi) { lo = 0; L = 0; }
        else {
            L = hi - lo + 1;
            #pragma unroll
            for (int s = 0; s < GRID; s++) {
                float g = ((float)s + 0.5f) / (float)GRID;
                float P = c1 + rs * g;
                if (P < -1.0f || P > (float)H) continue;
                float p = fminf(fmaxf(P, 0.0f), (float)(H - 1));
                int p0 = (int)floorf(p);
                int p1 = min(p0 + 1, H - 1);
                float lp = p - (float)p0;
                s_coef[r][axis][p0 - lo] += 1.0f - lp;
                s_coef[r][axis][p1 - lo] += lp;
            }
        }
        int base = (b * RSEL + r) * 8 + axis * 2;
        g_meta[base + 0] = lo;
        g_meta[base + 1] = L;

        if (axis == 1) {
            // compact cy: keep only nonzero (value, row-index) pairs
            int cnt = 0;
            for (int k = 0; k < L; k++) {
                float v = s_coef[r][1][k];
                if (v != 0.0f) {
                    s_coef[r][1][cnt] = v;
                    s_cyi[r][cnt] = k;
                    cnt++;
                }
            }
            g_meta[(b * RSEL + r) * 8 + 6] = cnt;   // Lc (after meta[6]=0 above)
        }
    }
    __syncthreads();

    // coalesced writeback (cy slots beyond Lc carry stale values; never read)
    for (int e = t; e < RSEL * 2 * SPAN; e += blockDim.x) {
        int r    = e / (2 * SPAN);
        int axis = (e >> 6) & 1;
        int k    = e & (SPAN - 1);
        if (axis) {
            g_cy [(b * RSEL + r) * SPAN + k] = s_coef[r][1][k];
            g_cyi[(b * RSEL + r) * SPAN + k] = s_cyi[r][k];
        } else {
            g_cx [(b * RSEL + r) * SPAN + k] = s_coef[r][0][k];
        }
    }
}

// ---------------------------------------------------------------------------
// K4: ROI pooling with compacted-y row list. Grid (RSEL, BATCH, NCGB=32) x 64.
// ---------------------------------------------------------------------------
__global__ void roi_pool_kernel(const float* __restrict__ f0,
                                const float* __restrict__ f1,
                                const float* __restrict__ f2,
                                const float* __restrict__ f3,
                                float* __restrict__ out)
{
    const int r   = blockIdx.x;
    const int b   = blockIdx.y;
    const int cg  = blockIdx.z;      // 8-channel group
    const int tid = threadIdx.x;     // 0..63
    const int idx = b * RSEL + r;

    const int4* mp4 = (const int4*)(g_meta + idx * 8);
    const int4 m0 = __ldg(mp4);      // xlo, Lx, ylo, Ly
    const int4 m1 = __ldg(mp4 + 1);  // valid, lv, Lc, 0

    float* outp = out + (size_t)idx * CCH + cg * 8;
    if (!m1.x) {
        if (tid < 8) outp[tid] = 0.0f;
        return;
    }

    const int xlo = m0.x, Lx = m0.y, ylo = m0.z;
    const int lv  = m1.y;
    const int Lc  = m1.z;            // compacted y-row count
    const int H   = 200 >> lv;
    const float* feat = (lv == 0) ? f0 : (lv == 1) ? f1 : (lv == 2) ? f2 : f3;
    const size_t hw = (size_t)H * (size_t)H;

    const float* cxp  = g_cx  + idx * SPAN;
    const float* cyp  = g_cy  + idx * SPAN;
    const int*   cyip = g_cyi + idx * SPAN;

    const int w    = tid >> 5;       // 0..1
    const int lane = tid & 31;
    const int xi   = lane & 15;
    const int yh   = lane >> 4;
    const int c0   = cg * 8 + w * 4;

    const float* bp = feat + ((size_t)b * CCH + c0) * hw
                    + (size_t)ylo * H + xlo;

    float a0 = 0.f, a1 = 0.f, a2 = 0.f, a3 = 0.f;
    for (int xb = xi; xb < Lx; xb += 16) {
        float cxv = __ldg(cxp + xb);
        float s0 = 0.f, s1 = 0.f, s2 = 0.f, s3 = 0.f;
        #pragma unroll 2
        for (int e = yh; e < Lc; e += 2) {
            float cyv = __ldg(cyp + e);
            int  row  = __ldg(cyip + e);
            const float* p = bp + (size_t)row * H + xb;
            s0 += cyv * __ldg(p);
            s1 += cyv * __ldg(p + hw);
            s2 += cyv * __ldg(p + 2 * hw);
            s3 += cyv * __ldg(p + 3 * hw);
        }
        a0 += s0 * cxv; a1 += s1 * cxv; a2 += s2 * cxv; a3 += s3 * cxv;
    }

    #pragma unroll
    for (int o = 16; o; o >>= 1) {
        a0 += __shfl_xor_sync(0xffffffffu, a0, o);
        a1 += __shfl_xor_sync(0xffffffffu, a1, o);
        a2 += __shfl_xor_sync(0xffffffffu, a2, o);
        a3 += __shfl_xor_sync(0xffffffffu, a3, o);
    }
    if (lane == 0) {
        const float sc = 1.0f / 196.0f;
        float4 v = make_float4(a0 * sc, a1 * sc, a2 * sc, a3 * sc);
        *(float4*)(outp + w * 4) = v;
    }
}

// ---------------------------------------------------------------------------
extern "C" void kernel_launch(void* const* d_in, const int* in_sizes, int n_in,
                              void* d_out, int out_size)
{
    const float* boxes  = (const float*)d_in[0];
    const float* scores = (const float*)d_in[1];
    const float* f0     = (const float*)d_in[2];
    const float* f1     = (const float*)d_in[3];
    const float* f2     = (const float*)d_in[4];
    const float* f3     = (const float*)d_in[5];
    float* out = (float*)d_out;

    k12_mask<<<dim3(NW, BATCH), 320>>>(boxes, scores);
    k3_final<<<BATCH, 320>>>();
    roi_pool_kernel<<<dim3(RSEL, BATCH, NCGB), 64>>>(f0, f1, f2, f3, out);
}

// round 17
// speedup vs baseline: 1.0478x; 1.0478x over previous
#include <cuda_runtime.h>
#include <math.h>

#define NB    300
#define BATCH 8
#define RSEL  36
#define NW    10
#define CCH   256
#define GRID  14
#define SPAN  64
#define NSEL  (BATCH * RSEL)
#define NCGB  32             // channel-group blocks (8 channels each)
#define CONF_THR 0.3f
#define IOU_THR  0.7f

// Inter-kernel scratch (device globals; no allocations allowed)
__device__ unsigned g_sup[BATCH * NB * NW];   // suppression masks
__device__ int      g_cnt[BATCH];             // mask-completion counters (zero-init)
__device__ float    g_cx[NSEL * SPAN];        // x coefficients
__device__ float    g_cy[NSEL * SPAN];        // y coefficients
__device__ int      g_meta[NSEL * 8];         // xlo,Lx,ylo,Ly,valid,lv,0,0

// ---------------------------------------------------------------------------
// K1: NMS, single kernel. Grid (NW+1, BATCH) x 320.
//  blocks w<NW : threshold + sort + suppression-mask word  (R9-proven body)
//  block  w==NW: own sort (overlapped), spin-wait for masks, sweep +
//                selection + level + separable coefficients (R9-proven body)
// ---------------------------------------------------------------------------
__global__ void nms_kernel(const float* __restrict__ boxes,
                           const float* __restrict__ scores)
{
    const int w = blockIdx.x;
    const int b = blockIdx.y;
    const int t = threadIdx.x;

    __shared__ float    s_raw[NB];
    __shared__ int      s_order[NB];
    __shared__ float4   s_box[NB];
    __shared__ float    s_area[NB];
    __shared__ float    s_ss[NB];
    __shared__ unsigned s_sup[NB][NW];
    __shared__ unsigned s_keepw[NW];
    __shared__ int      s_sel[RSEL];
    __shared__ float    s_coef[RSEL][2][SPAN];

    // --- common: threshold + stable rank sort + gather (all 88 blocks) ---
    for (int i = t; i < NB; i += blockDim.x) {
        float sc = scores[b * NB + i];
        s_raw[i] = (sc > CONF_THR) ? sc : -INFINITY;
    }
    __syncthreads();

    for (int i = t; i < NB; i += blockDim.x) {
        float si = s_raw[i];
        int rank = 0;
        for (int j = 0; j < NB; j++) {
            float sj = s_raw[j];
            if (sj > si || (sj == si && j < i)) rank++;
        }
        s_order[rank] = i;
    }
    __syncthreads();

    for (int r = t; r < NB; r += blockDim.x) {
        int i = s_order[r];
        float4 bb = ((const float4*)boxes)[(size_t)b * NB + i];
        s_box[r]  = bb;
        s_area[r] = (bb.z - bb.x) * (bb.w - bb.y);
        s_ss[r]   = s_raw[i];
    }
    __syncthreads();

    if (w < NW) {
        // ------------- mask block: word w of every row -------------
        const int i = t;
        if (i < NB) {
            unsigned bits = 0;
            if (w * 32 + 31 > i) {
                float4 a = s_box[i];
                float area_a = s_area[i];
                #pragma unroll 4
                for (int k = 0; k < 32; k++) {
                    int j = w * 32 + k;
                    if (j < NB && j > i) {
                        float4 bb = s_box[j];
                        float ltx = fmaxf(a.x, bb.x);
                        float lty = fmaxf(a.y, bb.y);
                        float rbx = fminf(a.z, bb.z);
                        float rby = fminf(a.w, bb.w);
                        float iw = fmaxf(rbx - ltx, 0.0f);
                        float ih = fmaxf(rby - lty, 0.0f);
                        float inter = iw * ih;
                        float iou = inter / (area_a + s_area[j] - inter + 1e-9f);
                        if (iou > IOU_THR) bits |= (1u << k);
                    }
                }
            }
            g_sup[(b * NB + i) * NW + w] = bits;
        }
        __syncthreads();
        if (t == 0) {
            __threadfence();                 // release mask stores
            atomicAdd(&g_cnt[b], 1);
        }
        return;
    }

    // ------------- finalizer block (w == NW) -------------
    // validity keep-words from local sorted scores
    if (t < 320) {
        int pred = (t < NB) && (s_ss[t] > -INFINITY);
        unsigned word = __ballot_sync(0xffffffffu, pred);
        if ((t & 31) == 0) s_keepw[t >> 5] = word;
    }
    for (int e = t; e < RSEL * 2 * SPAN; e += blockDim.x)
        ((float*)s_coef)[e] = 0.0f;

    // wait for all NW mask blocks of this batch
    if (t == 0) {
        while (atomicAdd(&g_cnt[b], 0) < NW) { }
        __threadfence();                     // acquire
        g_cnt[b] = 0;                        // reset for next replay (sole consumer)
    }
    __syncthreads();

    // stage suppression masks
    for (int e = t; e < NB * NW; e += blockDim.x)
        ((unsigned*)s_sup)[e] = g_sup[b * NB * NW + e];
    __syncthreads();

    // sequential greedy suppression (warp 0; lanes own keep-words)
    if (t < 32) {
        unsigned keepw = (t < NW) ? s_keepw[t] : 0u;
        for (int i = 0; i < NB; i++) {
            unsigned wv = __shfl_sync(0xffffffffu, keepw, i >> 5);
            if ((wv >> (i & 31)) & 1u) {
                if (t < NW) keepw &= ~s_sup[i][t];
            }
        }
        if (t < NW) s_keepw[t] = keepw;
    }
    __syncthreads();

    // stable partition: kept first, then suppressed
    if (t == 0) {
        int cnt = 0;
        for (int ww = 0; ww < NW && cnt < RSEL; ww++) {
            unsigned bits = s_keepw[ww];
            while (bits && cnt < RSEL) {
                int k = __ffs(bits) - 1; bits &= bits - 1;
                s_sel[cnt++] = ww * 32 + k;
            }
        }
        for (int ww = 0; ww < NW && cnt < RSEL; ww++) {
            unsigned bits = ~s_keepw[ww];
            if (ww == NW - 1) bits &= (1u << (NB - (NW - 1) * 32)) - 1;
            while (bits && cnt < RSEL) {
                int k = __ffs(bits) - 1; bits &= bits - 1;
                s_sel[cnt++] = ww * 32 + k;
            }
        }
    }
    __syncthreads();

    // selected boxes, validity, level -> meta
    if (t < RSEL) {
        int j = s_sel[t];
        float4 bb = s_box[j];
        int valid = (s_keepw[j >> 5] >> (j & 31)) & 1u;
        float dx = bb.z - bb.x, dy = bb.w - bb.y;
        float sz = sqrtf(fmaxf(dx * dx + dy * dy, 1e-12f));
        float lvf = fminf(fmaxf(floorf(4.0f + log2f(sz / 224.0f * 4.0f)), 2.0f), 5.0f);
        int base = (b * RSEL + t) * 8;
        g_meta[base + 4] = valid;
        g_meta[base + 5] = (int)lvf - 2;
        g_meta[base + 6] = 0;
        g_meta[base + 7] = 0;
    }
    __syncthreads();

    // separable coefficients: task t -> (box r = t>>1, axis = t&1)
    if (t < 2 * RSEL) {
        const int r = t >> 1, axis = t & 1;
        float4 bb = s_box[s_sel[r]];
        float dx = bb.z - bb.x, dy = bb.w - bb.y;
        float sz = sqrtf(fmaxf(dx * dx + dy * dy, 1e-12f));
        float lvf = fminf(fmaxf(floorf(4.0f + log2f(sz / 224.0f * 4.0f)), 2.0f), 5.0f);
        int lv = (int)lvf - 2;
        int H = 200 >> lv;
        float c1 = axis ? bb.y : bb.x;
        float c2 = axis ? bb.w : bb.z;
        float rs = fmaxf(c2 - c1, 1.0f);

        int lo = 1 << 30, hi = -(1 << 30);
        #pragma unroll
        for (int s = 0; s < GRID; s++) {
            float g = ((float)s + 0.5f) / (float)GRID;
            float P = c1 + rs * g;
            if (P < -1.0f || P > (float)H) continue;
            float p = fminf(fmaxf(P, 0.0f), (float)(H - 1));
            int p0 = (int)floorf(p);
            int p1 = min(p0 + 1, H - 1);
            lo = min(lo, p0); hi = max(hi, p1);
        }
        int L;
        if (lo > hi) { lo = 0; L = 0; }
        else {
            L = hi - lo + 1;
            #pragma unroll
            for (int s = 0; s < GRID; s++) {
                float g = ((float)s + 0.5f) / (float)GRID;
                float P = c1 + rs * g;
                if (P < -1.0f || P > (float)H) continue;
                float p = fminf(fmaxf(P, 0.0f), (float)(H - 1));
                int p0 = (int)floorf(p);
                int p1 = min(p0 + 1, H - 1);
                float lp = p - (float)p0;
                s_coef[r][axis][p0 - lo] += 1.0f - lp;
                s_coef[r][axis][p1 - lo] += lp;
            }
        }
        int base = (b * RSEL + r) * 8 + axis * 2;
        g_meta[base + 0] = lo;
        g_meta[base + 1] = L;
    }
    __syncthreads();

    // coalesced coefficient writeback
    for (int e = t; e < RSEL * 2 * SPAN; e += blockDim.x) {
        int r    = e / (2 * SPAN);
        int axis = (e >> 6) & 1;
        int k    = e & (SPAN - 1);
        float v  = s_coef[r][axis][k];
        if (axis) g_cy[(b * RSEL + r) * SPAN + k] = v;
        else      g_cx[(b * RSEL + r) * SPAN + k] = v;
    }
}

// ---------------------------------------------------------------------------
// K2: ROI pooling, stage-free. Grid (RSEL, BATCH, NCGB=32) x 64.
// int4 meta fetch; y-range loop (R13/R14 proven; best isolated measurement).
// ---------------------------------------------------------------------------
__global__ void roi_pool_kernel(const float* __restrict__ f0,
                                const float* __restrict__ f1,
                                const float* __restrict__ f2,
                                const float* __restrict__ f3,
                                float* __restrict__ out)
{
    const int r   = blockIdx.x;
    const int b   = blockIdx.y;
    const int cg  = blockIdx.z;      // 8-channel group
    const int tid = threadIdx.x;     // 0..63
    const int idx = b * RSEL + r;

    const int4* mp4 = (const int4*)(g_meta + idx * 8);
    const int4 m0 = __ldg(mp4);      // xlo, Lx, ylo, Ly
    const int4 m1 = __ldg(mp4 + 1);  // valid, lv, 0, 0

    float* outp = out + (size_t)idx * CCH + cg * 8;
    if (!m1.x) {
        if (tid < 8) outp[tid] = 0.0f;
        return;
    }

    const int xlo = m0.x, Lx = m0.y, ylo = m0.z, Ly = m0.w;
    const int lv  = m1.y;
    const int H   = 200 >> lv;
    const float* feat = (lv == 0) ? f0 : (lv == 1) ? f1 : (lv == 2) ? f2 : f3;
    const size_t hw = (size_t)H * (size_t)H;

    const float* cxp = g_cx + idx * SPAN;
    const float* cyp = g_cy + idx * SPAN;

    const int w    = tid >> 5;       // 0..1
    const int lane = tid & 31;
    const int xi   = lane & 15;
    const int yh   = lane >> 4;
    const int c0   = cg * 8 + w * 4;

    const float* bp = feat + ((size_t)b * CCH + c0) * hw
                    + (size_t)ylo * H + xlo;

    float a0 = 0.f, a1 = 0.f, a2 = 0.f, a3 = 0.f;
    for (int xb = xi; xb < Lx; xb += 16) {
        float cxv = __ldg(cxp + xb);
        float s0 = 0.f, s1 = 0.f, s2 = 0.f, s3 = 0.f;
        #pragma unroll 2
        for (int yy = yh; yy < Ly; yy += 2) {
            float cyv = __ldg(cyp + yy);
            const float* p = bp + (size_t)yy * H + xb;
            s0 += cyv * __ldg(p);
            s1 += cyv * __ldg(p + hw);
            s2 += cyv * __ldg(p + 2 * hw);
            s3 += cyv * __ldg(p + 3 * hw);
        }
        a0 += s0 * cxv; a1 += s1 * cxv; a2 += s2 * cxv; a3 += s3 * cxv;
    }

    #pragma unroll
    for (int o = 16; o; o >>= 1) {
        a0 += __shfl_xor_sync(0xffffffffu, a0, o);
        a1 += __shfl_xor_sync(0xffffffffu, a1, o);
        a2 += __shfl_xor_sync(0xffffffffu, a2, o);
        a3 += __shfl_xor_sync(0xffffffffu, a3, o);
    }
    if (lane == 0) {
        const float sc = 1.0f / 196.0f;
        float4 v = make_float4(a0 * sc, a1 * sc, a2 * sc, a3 * sc);
        *(float4*)(outp + w * 4) = v;
    }
}

// ---------------------------------------------------------------------------
extern "C" void kernel_launch(void* const* d_in, const int* in_sizes, int n_in,
                              void* d_out, int out_size)
{
    const float* boxes  = (const float*)d_in[0];
    const float* scores = (const float*)d_in[1];
    const float* f0     = (const float*)d_in[2];
    const float* f1     = (const float*)d_in[3];
    const float* f2     = (const float*)d_in[4];
    const float* f3     = (const float*)d_in[5];
    float* out = (float*)d_out;

    nms_kernel<<<dim3(NW + 1, BATCH), 320>>>(boxes, scores);
    roi_pool_kernel<<<dim3(RSEL, BATCH, NCGB), 64>>>(f0, f1, f2, f3, out);
}